// round 9
// baseline (speedup 1.0000x reference)
#include <cuda_runtime.h>
#include <cuda_fp16.h>
#include <cstdint>

#define NT 4096   // tokens
#define DM 1024   // model dim
#define DF 4096   // ffn dim

// ---- scratch (static device globals; allowed) ----
__device__ __half g_Eh[(size_t)NT * DM];
__device__ __half g_QKVh[(size_t)NT * 3072];      // fused Q|K|V (half), stride 3072
__device__ float  g_S[(size_t)NT * NT];           // attention scores fp32
__device__ __half g_Sh[(size_t)NT * NT];          // softmax probs half
__device__ float  g_AE[NT * DM];
__device__ __half g_Xh[NT * DM];
__device__ __half g_Hh[(size_t)NT * DF];
__device__ __half g_Wqkvth[3072 * DM];            // [3072][1024] W^T half
__device__ __half g_W1th[(size_t)DF * DM];        // [4096][1024]
__device__ __half g_W2th[(size_t)DM * DF];        // [1024][4096]
__device__ __half g_Vth[(size_t)DM * NT];         // [1024][4096] V^T half
__device__ float  g_bqkv[3072];

__device__ __forceinline__ uint32_t smem_u32(const void* p) {
    uint32_t a;
    asm("{ .reg .u64 t; cvta.to.shared.u64 t, %1; cvt.u32.u64 %0, t; }" : "=r"(a) : "l"(p));
    return a;
}
__device__ __forceinline__ void mma_f16(float* c, const uint32_t* a, const uint32_t* b) {
    asm volatile(
        "mma.sync.aligned.m16n8k16.row.col.f32.f16.f16.f32 "
        "{%0,%1,%2,%3}, {%4,%5,%6,%7}, {%8,%9}, {%0,%1,%2,%3};"
        : "+f"(c[0]), "+f"(c[1]), "+f"(c[2]), "+f"(c[3])
        : "r"(a[0]), "r"(a[1]), "r"(a[2]), "r"(a[3]), "r"(b[0]), "r"(b[1]));
}
__device__ __forceinline__ void ldsm4(uint32_t& r0, uint32_t& r1, uint32_t& r2, uint32_t& r3,
                                      uint32_t addr) {
    asm volatile("ldmatrix.sync.aligned.m8n8.x4.shared.b16 {%0,%1,%2,%3}, [%4];"
                 : "=r"(r0), "=r"(r1), "=r"(r2), "=r"(r3) : "r"(addr));
}

// ===========================================================================
// fp16 mma.sync GEMM, LDG->STS double buffer.
//   C[M,N] = alpha * A[M,K] @ Bt[N,K]^T (+bias) (+relu); A,Bt half in gmem.
// Tiles 128x128x32, 128 threads = 4 warps in 2x2 -> 64x64 warp tiles
//   (minimizes smem fragment-read redundancy: A read 2x, B read 2x).
// occ 2 => 256 threads/SM => 256 regs/thread: fits 128-reg acc + buffers.
// Smem row = 32 half = 64B = 4 chunks; swizzle c_phys = c ^ ((r>>1)&3).
// ===========================================================================
template <bool CAUSAL, bool TRIK, bool RELU, bool BIAS, bool HALF_OUT>
__global__ __launch_bounds__(128, 2)
void hgemm2(const __half* __restrict__ A, const __half* __restrict__ Bt,
            const float* __restrict__ bias, void* __restrict__ Cv,
            int N, int Kdim, int lda, int ldb, float alpha)
{
    __shared__ __align__(16) uint32_t As[2][2048];   // 2 bufs x 128 rows x 16 words
    __shared__ __align__(16) uint32_t Bs[2][2048];

    const int bx = blockIdx.x, by = blockIdx.y;
    if (CAUSAL && bx > by) return;

    const int tid  = threadIdx.x;
    const int wid  = tid >> 5;
    const int lane = tid & 31;
    const int g    = lane >> 2;
    const int tig  = lane & 3;
    const int l7   = lane & 7;
    const int q    = lane >> 3;

    const int wmt = (wid & 1) * 4;        // first m16-tile (2 m-slabs of 64)
    const int wnt = (wid >> 1) * 8;       // first n8-tile  (2 n-slabs of 64)

    int kEnd = Kdim;
    if (TRIK) { int lim = (by + 1) * 128; kEnd = lim < Kdim ? lim : Kdim; }
    const int niter = kEnd >> 5;

    // copy side: thread owns one 128-row tile row => 4 chunks of 16B each
    const __half* aG = A  + (size_t)(by * 128 + tid) * (size_t)lda;
    const __half* bG = Bt + (size_t)(bx * 128 + tid) * (size_t)ldb;
    int wofs[4];
#pragma unroll
    for (int c = 0; c < 4; c++)
        wofs[c] = tid * 16 + ((c ^ ((tid >> 1) & 3)) << 2);

    uint4 ra[4], rb[4];
#define LDG_T(k0) do { \
        _Pragma("unroll") \
        for (int c = 0; c < 4; c++) { \
            ra[c] = *(const uint4*)(aG + (k0) + c * 8); \
            rb[c] = *(const uint4*)(bG + (k0) + c * 8); \
        } } while (0)
#define STS_T(buf) do { \
        _Pragma("unroll") \
        for (int c = 0; c < 4; c++) { \
            *(uint4*)&As[buf][wofs[c]] = ra[c]; \
            *(uint4*)&Bs[buf][wofs[c]] = rb[c]; \
        } } while (0)

    const uint32_t aSm = smem_u32(As);
    const uint32_t bSm = smem_u32(Bs);

    // ldmatrix lane byte-offsets (relative to buffer base)
    uint32_t aOff[4][2], bOff[4][2];
#pragma unroll
    for (int m = 0; m < 4; m++) {
        int r = (wmt + m) * 16 + (q & 1) * 8 + l7;
#pragma unroll
        for (int ks = 0; ks < 2; ks++) {
            uint32_t c = (uint32_t)(2 * ks) + (uint32_t)(q >> 1);
            aOff[m][ks] = (uint32_t)r * 64u + ((c ^ ((uint32_t)(r >> 1) & 3u)) << 4);
        }
    }
#pragma unroll
    for (int p = 0; p < 4; p++) {         // each ldsm4 covers 2 n8-tiles
        int r = (wnt + 2 * p + (q >> 1)) * 8 + l7;
#pragma unroll
        for (int ks = 0; ks < 2; ks++) {
            uint32_t c = (uint32_t)(2 * ks) + (uint32_t)(q & 1);
            bOff[p][ks] = (uint32_t)r * 64u + ((c ^ ((uint32_t)(r >> 1) & 3u)) << 4);
        }
    }

    float acc[4][8][4];
#pragma unroll
    for (int i = 0; i < 4; i++)
#pragma unroll
        for (int j = 0; j < 8; j++)
#pragma unroll
            for (int t = 0; t < 4; t++) acc[i][j][t] = 0.f;

    LDG_T(0);
    STS_T(0);
    __syncthreads();

    for (int i = 0; i < niter; i++) {
        const int b = i & 1;
        if (i + 1 < niter) LDG_T((i + 1) * 32);

        const uint32_t aBase = aSm + (uint32_t)b * 8192u;
        const uint32_t bBase = bSm + (uint32_t)b * 8192u;
#pragma unroll
        for (int ks = 0; ks < 2; ks++) {
            uint32_t af[4][4], bf[8][2];
#pragma unroll
            for (int m = 0; m < 4; m++)
                ldsm4(af[m][0], af[m][1], af[m][2], af[m][3], aBase + aOff[m][ks]);
#pragma unroll
            for (int p = 0; p < 4; p++)
                ldsm4(bf[2 * p][0], bf[2 * p][1], bf[2 * p + 1][0], bf[2 * p + 1][1],
                      bBase + bOff[p][ks]);
#pragma unroll
            for (int m = 0; m < 4; m++)
#pragma unroll
                for (int n = 0; n < 8; n++)
                    mma_f16(acc[m][n], af[m], bf[n]);
        }

        if (i + 1 < niter) STS_T(b ^ 1);
        __syncthreads();
    }

    // ---- epilogue ----
    const int rowBase = by * 128 + (wid & 1) * 64 + g;
    const int colBase = bx * 128 + (wid >> 1) * 64 + tig * 2;
#pragma unroll
    for (int m = 0; m < 4; m++) {
        const int r0 = rowBase + m * 16;
#pragma unroll
        for (int n = 0; n < 8; n++) {
            const int col = colBase + n * 8;
            float b0 = 0.f, b1 = 0.f;
            if (BIAS) { b0 = bias[col]; b1 = bias[col + 1]; }
            float v0x = acc[m][n][0] * alpha + b0;
            float v0y = acc[m][n][1] * alpha + b1;
            float v1x = acc[m][n][2] * alpha + b0;
            float v1y = acc[m][n][3] * alpha + b1;
            if (RELU) {
                v0x = fmaxf(v0x, 0.f); v0y = fmaxf(v0y, 0.f);
                v1x = fmaxf(v1x, 0.f); v1y = fmaxf(v1y, 0.f);
            }
            if (HALF_OUT) {
                __half* C = (__half*)Cv;
                *(__half2*)(C + (size_t)r0 * N + col)       = __floats2half2_rn(v0x, v0y);
                *(__half2*)(C + (size_t)(r0 + 8) * N + col) = __floats2half2_rn(v1x, v1y);
            } else {
                float* C = (float*)Cv;
                *(float2*)(C + (size_t)r0 * N + col)       = make_float2(v0x, v0y);
                *(float2*)(C + (size_t)(r0 + 8) * N + col) = make_float2(v1x, v1y);
            }
        }
    }
#undef LDG_T
#undef STS_T
}

// ============ fp32 -> fp16 convert ============
__global__ void f2h(const float* __restrict__ in, __half* __restrict__ out, int n4)
{
    int i = blockIdx.x * blockDim.x + threadIdx.x;
    if (i < n4) {
        float4 v = ((const float4*)in)[i];
        ((__half2*)out)[i * 2]     = __floats2half2_rn(v.x, v.y);
        ((__half2*)out)[i * 2 + 1] = __floats2half2_rn(v.z, v.w);
    }
}

// ============ transpose fp32 -> fp16: out[c][r] = in[r][c] ============
__global__ void transpose_f2h(const float* __restrict__ in, __half* __restrict__ out,
                              int inS, int outS)
{
    __shared__ float t[32][33];
    const int bc = blockIdx.x * 32;
    const int br = blockIdx.y * 32;
    const int x = threadIdx.x, y = threadIdx.y;
#pragma unroll
    for (int j = 0; j < 32; j += 8)
        t[y + j][x] = in[(size_t)(br + y + j) * inS + bc + x];
    __syncthreads();
#pragma unroll
    for (int j = 0; j < 32; j += 8)
        out[(size_t)(bc + y + j) * outS + br + x] = __float2half(t[x][y + j]);
}

// ============ transpose fp16 -> fp16 ============
__global__ void transpose_h2h(const __half* __restrict__ in, __half* __restrict__ out,
                              int inS, int outS)
{
    __shared__ __half t[32][34];
    const int bc = blockIdx.x * 32;
    const int br = blockIdx.y * 32;
    const int x = threadIdx.x, y = threadIdx.y;
#pragma unroll
    for (int j = 0; j < 32; j += 8)
        t[y + j][x] = in[(size_t)(br + y + j) * inS + bc + x];
    __syncthreads();
#pragma unroll
    for (int j = 0; j < 32; j += 8)
        out[(size_t)(bc + y + j) * outS + br + x] = t[x][y + j];
}

// ============ fast exp (FMA pipe) ============
__device__ __forceinline__ float fast_exp(float x) {
    float y = x * 1.4426950408889634f;
    float n = rintf(y);
    float f = y - n;
    float p = 1.5403530393e-4f;
    p = fmaf(p, f, 1.3333558146e-3f);
    p = fmaf(p, f, 9.6181291076e-3f);
    p = fmaf(p, f, 5.5504108665e-2f);
    p = fmaf(p, f, 2.4022650696e-1f);
    p = fmaf(p, f, 6.9314718056e-1f);
    p = fmaf(p, f, 1.0f);
    float ec = fmaxf(n, -126.f);
    return __int_as_float(((int)ec + 127) << 23) * p;
}

// ============ causal softmax: fp32 scores -> fp16 probs (zero-padded) ============
__global__ void softmax_causal(const float* __restrict__ S, __half* __restrict__ Sh)
{
    const int r = blockIdx.x;
    const int tid = threadIdx.x;
    const int limit = ((r >> 7) + 1) << 7;
    const float* row = S + (size_t)r * NT;
    __half* rowh = Sh + (size_t)r * NT;

    float vals[16];
    int n = 0;
    float m = -1e30f;
    for (int j = tid; j < limit; j += 256) {
        float v = (j <= r) ? row[j] : -1e30f;
        vals[n++] = v;
        m = fmaxf(m, v);
    }
    __shared__ float redm[8], reds[8];
#pragma unroll
    for (int o = 16; o > 0; o >>= 1) m = fmaxf(m, __shfl_xor_sync(0xffffffffu, m, o));
    if ((tid & 31) == 0) redm[tid >> 5] = m;
    __syncthreads();
    m = redm[0];
#pragma unroll
    for (int i = 1; i < 8; i++) m = fmaxf(m, redm[i]);

    float s = 0.f;
    for (int i = 0; i < n; i++) { float e = fast_exp(vals[i] - m); vals[i] = e; s += e; }
#pragma unroll
    for (int o = 16; o > 0; o >>= 1) s += __shfl_xor_sync(0xffffffffu, s, o);
    if ((tid & 31) == 0) reds[tid >> 5] = s;
    __syncthreads();
    s = reds[0];
#pragma unroll
    for (int i = 1; i < 8; i++) s += reds[i];

    const float inv = 1.f / s;
    n = 0;
    for (int j = tid; j < limit; j += 256) rowh[j] = __float2half(vals[n++] * inv);
}

// ============ add + LayerNorm -> fp16 X ============
__global__ void add_layernorm(const float* __restrict__ AE, const float* __restrict__ E,
                              const float* __restrict__ gamma, const float* __restrict__ beta,
                              __half* __restrict__ X)
{
    const int r = blockIdx.x;
    const int tid = threadIdx.x;
    float4 a = ((const float4*)(AE + (size_t)r * DM))[tid];
    float4 e = ((const float4*)(E + (size_t)r * DM))[tid];
    float x0 = a.x + e.x, x1 = a.y + e.y, x2 = a.z + e.z, x3 = a.w + e.w;
    float s = x0 + x1 + x2 + x3;
    float q = x0 * x0 + x1 * x1 + x2 * x2 + x3 * x3;
    __shared__ float rs[8], rq[8];
#pragma unroll
    for (int o = 16; o > 0; o >>= 1) {
        s += __shfl_xor_sync(0xffffffffu, s, o);
        q += __shfl_xor_sync(0xffffffffu, q, o);
    }
    if ((tid & 31) == 0) { rs[tid >> 5] = s; rq[tid >> 5] = q; }
    __syncthreads();
    s = rs[0]; q = rq[0];
#pragma unroll
    for (int i = 1; i < 8; i++) { s += rs[i]; q += rq[i]; }
    const float mean = s * (1.f / DM);
    const float var  = q * (1.f / DM) - mean * mean;
    const float inv  = rsqrtf(var + 1e-5f);
    float4 gg = ((const float4*)gamma)[tid];
    float4 bb = ((const float4*)beta)[tid];
    __half2 o0 = __floats2half2_rn((x0 - mean) * inv * gg.x + bb.x,
                                   (x1 - mean) * inv * gg.y + bb.y);
    __half2 o1 = __floats2half2_rn((x2 - mean) * inv * gg.z + bb.z,
                                   (x3 - mean) * inv * gg.w + bb.w);
    ((__half2*)(X + (size_t)r * DM))[tid * 2]     = o0;
    ((__half2*)(X + (size_t)r * DM))[tid * 2 + 1] = o1;
}

// ============ launch ============
extern "C" void kernel_launch(void* const* d_in, const int* in_sizes, int n_in,
                              void* d_out, int out_size)
{
    (void)in_sizes; (void)n_in; (void)out_size;
    const float* E     = (const float*)d_in[0];
    const float* Wq    = (const float*)d_in[1];
    const float* bq    = (const float*)d_in[2];
    const float* Wk    = (const float*)d_in[3];
    const float* bk    = (const float*)d_in[4];
    const float* Wv    = (const float*)d_in[5];
    const float* bv    = (const float*)d_in[6];
    const float* gamma = (const float*)d_in[7];
    const float* beta  = (const float*)d_in[8];
    const float* W1    = (const float*)d_in[9];
    const float* b1    = (const float*)d_in[10];
    const float* W2    = (const float*)d_in[11];
    const float* b2    = (const float*)d_in[12];
    float* out = (float*)d_out;

    __half *Eh, *QKVh, *Sh, *Xh, *Hh, *Wqkvth, *W1th, *W2th, *Vth;
    float *S, *AE, *bqkv;
    cudaGetSymbolAddress((void**)&Eh,     g_Eh);
    cudaGetSymbolAddress((void**)&QKVh,   g_QKVh);
    cudaGetSymbolAddress((void**)&S,      g_S);
    cudaGetSymbolAddress((void**)&Sh,     g_Sh);
    cudaGetSymbolAddress((void**)&AE,     g_AE);
    cudaGetSymbolAddress((void**)&Xh,     g_Xh);
    cudaGetSymbolAddress((void**)&Hh,     g_Hh);
    cudaGetSymbolAddress((void**)&Wqkvth, g_Wqkvth);
    cudaGetSymbolAddress((void**)&W1th,   g_W1th);
    cudaGetSymbolAddress((void**)&W2th,   g_W2th);
    cudaGetSymbolAddress((void**)&Vth,    g_Vth);
    cudaGetSymbolAddress((void**)&bqkv,   g_bqkv);

    dim3 tb(32, 8);
    f2h<<<(NT * DM / 4 + 255) / 256, 256>>>(E, Eh, NT * DM / 4);
    transpose_f2h<<<dim3(DM / 32, DM / 32), tb>>>(Wq, Wqkvth,             DM, DM);
    transpose_f2h<<<dim3(DM / 32, DM / 32), tb>>>(Wk, Wqkvth + 1024 * DM, DM, DM);
    transpose_f2h<<<dim3(DM / 32, DM / 32), tb>>>(Wv, Wqkvth + 2048 * DM, DM, DM);
    transpose_f2h<<<dim3(DF / 32, DM / 32), tb>>>(W1, W1th,               DF, DM);
    transpose_f2h<<<dim3(DM / 32, DF / 32), tb>>>(W2, W2th,               DM, DF);
    cudaMemcpyAsync(bqkv,        bq, DM * sizeof(float), cudaMemcpyDeviceToDevice);
    cudaMemcpyAsync(bqkv + 1024, bk, DM * sizeof(float), cudaMemcpyDeviceToDevice);
    cudaMemcpyAsync(bqkv + 2048, bv, DM * sizeof(float), cudaMemcpyDeviceToDevice);

    dim3 blk(128);

    // fused QKV projection -> half [4096, 3072]
    hgemm2<false, false, false, true, true><<<dim3(3072 / 128, NT / 128), blk>>>(
        Eh, Wqkvth, bqkv, QKVh, 3072, DM, DM, DM, 1.f);

    // S = Q @ K^T / 32 (causal lower blocks) -> fp32
    hgemm2<true, false, false, false, false><<<dim3(NT / 128, NT / 128), blk>>>(
        QKVh, QKVh + 1024, nullptr, S, NT, DM, 3072, 3072, 0.03125f);

    softmax_causal<<<NT, 256>>>(S, Sh);

    // Vth[d][t] = V[t][d]
    transpose_h2h<<<dim3(DM / 32, NT / 32), tb>>>(QKVh + 2048, Vth, 3072, NT);

    // AE = probs @ V (triangular K) -> fp32
    hgemm2<false, true, false, false, false><<<dim3(DM / 128, NT / 128), blk>>>(
        Sh, Vth, nullptr, AE, DM, NT, NT, NT, 1.f);

    add_layernorm<<<NT, 256>>>(AE, E, gamma, beta, Xh);

    // FFN
    hgemm2<false, false, true, true, true><<<dim3(DF / 128, NT / 128), blk>>>(
        Xh, W1th, b1, Hh, DF, DM, DM, DM, 1.f);
    hgemm2<false, false, false, true, false><<<dim3(DM / 128, NT / 128), blk>>>(
        Hh, W2th, b2, out, DM, DF, DF, DF, 1.f);
}

// round 10
// speedup vs baseline: 1.5204x; 1.5204x over previous
#include <cuda_runtime.h>
#include <cuda_fp16.h>
#include <cstdint>

#define NT 4096   // tokens
#define DM 1024   // model dim
#define DF 4096   // ffn dim

// ---- scratch (static device globals; allowed) ----
__device__ __half g_Eh[(size_t)NT * DM];
__device__ __half g_QKVh[(size_t)NT * 3072];      // fused Q|K|V (half), stride 3072
__device__ float  g_S[(size_t)NT * NT];           // attention scores fp32
__device__ __half g_Sh[(size_t)NT * NT];          // softmax probs half
__device__ float  g_AE[NT * DM];
__device__ __half g_Xh[NT * DM];
__device__ __half g_Hh[(size_t)NT * DF];
__device__ __half g_Wqkvth[3072 * DM];            // [3072][1024] W^T half
__device__ __half g_W1th[(size_t)DF * DM];        // [4096][1024]
__device__ __half g_W2th[(size_t)DM * DF];        // [1024][4096]
__device__ __half g_Vth[(size_t)DM * NT];         // [1024][4096] V^T half
__device__ float  g_bqkv[3072];

__device__ __forceinline__ uint32_t smem_u32(const void* p) {
    uint32_t a;
    asm("{ .reg .u64 t; cvta.to.shared.u64 t, %1; cvt.u32.u64 %0, t; }" : "=r"(a) : "l"(p));
    return a;
}
__device__ __forceinline__ void mma_f16(float* c, const uint32_t* a, const uint32_t* b) {
    asm volatile(
        "mma.sync.aligned.m16n8k16.row.col.f32.f16.f16.f32 "
        "{%0,%1,%2,%3}, {%4,%5,%6,%7}, {%8,%9}, {%0,%1,%2,%3};"
        : "+f"(c[0]), "+f"(c[1]), "+f"(c[2]), "+f"(c[3])
        : "r"(a[0]), "r"(a[1]), "r"(a[2]), "r"(a[3]), "r"(b[0]), "r"(b[1]));
}
__device__ __forceinline__ void ldsm4(uint32_t& r0, uint32_t& r1, uint32_t& r2, uint32_t& r3,
                                      uint32_t addr) {
    asm volatile("ldmatrix.sync.aligned.m8n8.x4.shared.b16 {%0,%1,%2,%3}, [%4];"
                 : "=r"(r0), "=r"(r1), "=r"(r2), "=r"(r3) : "r"(addr));
}

// ===========================================================================
// fp16 mma.sync GEMM, LDG->STS 3-buffer smem ring (STS-early ordering:
//   per iter  STS(tile i+1) ; LDG(tile i+2) ; compute(tile i) ; sync
// so LDG->STS coverage = one full iteration).
//   C[M,N] = alpha * A[M,K] @ Bt[N,K]^T (+bias) (+relu); A,Bt half in gmem.
// Tiles 128x128x32, 256 threads = 8 warps (2 m-slabs x 4 n-slabs, 64x32 each),
// occ 2 -> 16 warps/SM (R8 config: latency hiding beats crossbar bytes).
// Smem tile row = 32 half = 64B = 4 chunks; swizzle c_phys = c ^ ((r>>1)&3).
// ===========================================================================
template <bool CAUSAL, bool TRIK, bool RELU, bool BIAS, bool HALF_OUT>
__global__ __launch_bounds__(256, 2)
void hgemm2(const __half* __restrict__ A, const __half* __restrict__ Bt,
            const float* __restrict__ bias, void* __restrict__ Cv,
            int N, int Kdim, int lda, int ldb, float alpha)
{
    __shared__ __align__(16) uint32_t As[3][2048];   // 3 bufs x 128 rows x 16 words
    __shared__ __align__(16) uint32_t Bs[3][2048];   // total 48KB

    const int bx = blockIdx.x, by = blockIdx.y;
    if (CAUSAL && bx > by) return;

    const int tid  = threadIdx.x;
    const int wid  = tid >> 5;
    const int lane = tid & 31;
    const int g    = lane >> 2;
    const int tig  = lane & 3;
    const int l7   = lane & 7;
    const int q    = lane >> 3;

    const int wmt = (wid & 1) * 4;        // first m16-tile (2 slabs of 64)
    const int wnt = (wid >> 1) * 4;       // first n8-tile  (4 slabs of 32)

    int kEnd = Kdim;
    if (TRIK) { int lim = (by + 1) * 128; kEnd = lim < Kdim ? lim : Kdim; }
    const int niter = kEnd >> 5;

    // copy side: 512 16B-chunks per operand tile, 2 per thread
    const int r0c = tid >> 2, c0c = tid & 3;          // chunk set 0: rows 0..63
    const int w0 = r0c * 16 + ((c0c ^ ((r0c >> 1) & 3)) << 2);
    const int r1c = r0c + 64;
    const int w1 = r1c * 16 + ((c0c ^ ((r1c >> 1) & 3)) << 2);
    const __half* aG0 = A  + (size_t)(by * 128 + r0c) * (size_t)lda + c0c * 8;
    const __half* aG1 = A  + (size_t)(by * 128 + r1c) * (size_t)lda + c0c * 8;
    const __half* bG0 = Bt + (size_t)(bx * 128 + r0c) * (size_t)ldb + c0c * 8;
    const __half* bG1 = Bt + (size_t)(bx * 128 + r1c) * (size_t)ldb + c0c * 8;

    uint4 ra0, ra1, rb0, rb1;
#define LDG_T(k0) do { \
        ra0 = *(const uint4*)(aG0 + (k0)); \
        ra1 = *(const uint4*)(aG1 + (k0)); \
        rb0 = *(const uint4*)(bG0 + (k0)); \
        rb1 = *(const uint4*)(bG1 + (k0)); \
    } while (0)
#define STS_T(buf) do { \
        *(uint4*)&As[buf][w0] = ra0; \
        *(uint4*)&As[buf][w1] = ra1; \
        *(uint4*)&Bs[buf][w0] = rb0; \
        *(uint4*)&Bs[buf][w1] = rb1; \
    } while (0)

    const uint32_t aSm = smem_u32(As);
    const uint32_t bSm = smem_u32(Bs);

    // ldmatrix lane byte-offsets (relative to buffer base)
    uint32_t aOff[4][2], bOff[2][2];
#pragma unroll
    for (int m = 0; m < 4; m++) {
        int r = (wmt + m) * 16 + (q & 1) * 8 + l7;
#pragma unroll
        for (int ks = 0; ks < 2; ks++) {
            uint32_t c = (uint32_t)(2 * ks) + (uint32_t)(q >> 1);
            aOff[m][ks] = (uint32_t)r * 64u + ((c ^ ((uint32_t)(r >> 1) & 3u)) << 4);
        }
    }
#pragma unroll
    for (int p = 0; p < 2; p++) {
        int r = (wnt + 2 * p + (q >> 1)) * 8 + l7;
#pragma unroll
        for (int ks = 0; ks < 2; ks++) {
            uint32_t c = (uint32_t)(2 * ks) + (uint32_t)(q & 1);
            bOff[p][ks] = (uint32_t)r * 64u + ((c ^ ((uint32_t)(r >> 1) & 3u)) << 4);
        }
    }

    float acc[4][4][4];
#pragma unroll
    for (int i = 0; i < 4; i++)
#pragma unroll
        for (int j = 0; j < 4; j++)
#pragma unroll
            for (int t = 0; t < 4; t++) acc[i][j][t] = 0.f;

    // prologue: tile0 -> buf0; tile1 held in regs
    LDG_T(0);
    STS_T(0);
    if (niter > 1) LDG_T(32);
    __syncthreads();

    int bufC = 0, bufS = 1;
    for (int i = 0; i < niter; i++) {
        if (i + 1 < niter) STS_T(bufS);          // store tile i+1 (regs from last iter)
        if (i + 2 < niter) LDG_T((i + 2) * 32);  // fetch tile i+2 (full iter to land)

        const uint32_t aBase = aSm + (uint32_t)bufC * 8192u;
        const uint32_t bBase = bSm + (uint32_t)bufC * 8192u;
#pragma unroll
        for (int ks = 0; ks < 2; ks++) {
            uint32_t af[4][4], bf[4][2];
#pragma unroll
            for (int m = 0; m < 4; m++)
                ldsm4(af[m][0], af[m][1], af[m][2], af[m][3], aBase + aOff[m][ks]);
#pragma unroll
            for (int p = 0; p < 2; p++)
                ldsm4(bf[2 * p][0], bf[2 * p][1], bf[2 * p + 1][0], bf[2 * p + 1][1],
                      bBase + bOff[p][ks]);
#pragma unroll
            for (int m = 0; m < 4; m++)
#pragma unroll
                for (int n = 0; n < 4; n++)
                    mma_f16(acc[m][n], af[m], bf[n]);
        }

        __syncthreads();
        bufC = (bufC == 2) ? 0 : bufC + 1;
        bufS = (bufS == 2) ? 0 : bufS + 1;
    }

    // ---- epilogue ----
    const int rowBase = by * 128 + (wid & 1) * 64 + g;
    const int colBase = bx * 128 + (wid >> 1) * 32 + tig * 2;
#pragma unroll
    for (int m = 0; m < 4; m++) {
        const int r0 = rowBase + m * 16;
#pragma unroll
        for (int n = 0; n < 4; n++) {
            const int col = colBase + n * 8;
            float b0 = 0.f, b1 = 0.f;
            if (BIAS) { b0 = bias[col]; b1 = bias[col + 1]; }
            float v0x = acc[m][n][0] * alpha + b0;
            float v0y = acc[m][n][1] * alpha + b1;
            float v1x = acc[m][n][2] * alpha + b0;
            float v1y = acc[m][n][3] * alpha + b1;
            if (RELU) {
                v0x = fmaxf(v0x, 0.f); v0y = fmaxf(v0y, 0.f);
                v1x = fmaxf(v1x, 0.f); v1y = fmaxf(v1y, 0.f);
            }
            if (HALF_OUT) {
                __half* C = (__half*)Cv;
                *(__half2*)(C + (size_t)r0 * N + col)       = __floats2half2_rn(v0x, v0y);
                *(__half2*)(C + (size_t)(r0 + 8) * N + col) = __floats2half2_rn(v1x, v1y);
            } else {
                float* C = (float*)Cv;
                *(float2*)(C + (size_t)r0 * N + col)       = make_float2(v0x, v0y);
                *(float2*)(C + (size_t)(r0 + 8) * N + col) = make_float2(v1x, v1y);
            }
        }
    }
#undef LDG_T
#undef STS_T
}

// ============ fp32 -> fp16 convert ============
__global__ void f2h(const float* __restrict__ in, __half* __restrict__ out, int n4)
{
    int i = blockIdx.x * blockDim.x + threadIdx.x;
    if (i < n4) {
        float4 v = ((const float4*)in)[i];
        ((__half2*)out)[i * 2]     = __floats2half2_rn(v.x, v.y);
        ((__half2*)out)[i * 2 + 1] = __floats2half2_rn(v.z, v.w);
    }
}

// ============ transpose fp32 -> fp16: out[c][r] = in[r][c] ============
__global__ void transpose_f2h(const float* __restrict__ in, __half* __restrict__ out,
                              int inS, int outS)
{
    __shared__ float t[32][33];
    const int bc = blockIdx.x * 32;
    const int br = blockIdx.y * 32;
    const int x = threadIdx.x, y = threadIdx.y;
#pragma unroll
    for (int j = 0; j < 32; j += 8)
        t[y + j][x] = in[(size_t)(br + y + j) * inS + bc + x];
    __syncthreads();
#pragma unroll
    for (int j = 0; j < 32; j += 8)
        out[(size_t)(bc + y + j) * outS + br + x] = __float2half(t[x][y + j]);
}

// ============ transpose fp16 -> fp16 ============
__global__ void transpose_h2h(const __half* __restrict__ in, __half* __restrict__ out,
                              int inS, int outS)
{
    __shared__ __half t[32][34];
    const int bc = blockIdx.x * 32;
    const int br = blockIdx.y * 32;
    const int x = threadIdx.x, y = threadIdx.y;
#pragma unroll
    for (int j = 0; j < 32; j += 8)
        t[y + j][x] = in[(size_t)(br + y + j) * inS + bc + x];
    __syncthreads();
#pragma unroll
    for (int j = 0; j < 32; j += 8)
        out[(size_t)(bc + y + j) * outS + br + x] = t[x][y + j];
}

// ============ fast exp (FMA pipe) ============
__device__ __forceinline__ float fast_exp(float x) {
    float y = x * 1.4426950408889634f;
    float n = rintf(y);
    float f = y - n;
    float p = 1.5403530393e-4f;
    p = fmaf(p, f, 1.3333558146e-3f);
    p = fmaf(p, f, 9.6181291076e-3f);
    p = fmaf(p, f, 5.5504108665e-2f);
    p = fmaf(p, f, 2.4022650696e-1f);
    p = fmaf(p, f, 6.9314718056e-1f);
    p = fmaf(p, f, 1.0f);
    float ec = fmaxf(n, -126.f);
    return __int_as_float(((int)ec + 127) << 23) * p;
}

// ============ causal softmax: fp32 scores -> fp16 probs (zero-padded) ============
__global__ void softmax_causal(const float* __restrict__ S, __half* __restrict__ Sh)
{
    const int r = blockIdx.x;
    const int tid = threadIdx.x;
    const int limit = ((r >> 7) + 1) << 7;
    const float* row = S + (size_t)r * NT;
    __half* rowh = Sh + (size_t)r * NT;

    float vals[16];
    int n = 0;
    float m = -1e30f;
    for (int j = tid; j < limit; j += 256) {
        float v = (j <= r) ? row[j] : -1e30f;
        vals[n++] = v;
        m = fmaxf(m, v);
    }
    __shared__ float redm[8], reds[8];
#pragma unroll
    for (int o = 16; o > 0; o >>= 1) m = fmaxf(m, __shfl_xor_sync(0xffffffffu, m, o));
    if ((tid & 31) == 0) redm[tid >> 5] = m;
    __syncthreads();
    m = redm[0];
#pragma unroll
    for (int i = 1; i < 8; i++) m = fmaxf(m, redm[i]);

    float s = 0.f;
    for (int i = 0; i < n; i++) { float e = fast_exp(vals[i] - m); vals[i] = e; s += e; }
#pragma unroll
    for (int o = 16; o > 0; o >>= 1) s += __shfl_xor_sync(0xffffffffu, s, o);
    if ((tid & 31) == 0) reds[tid >> 5] = s;
    __syncthreads();
    s = reds[0];
#pragma unroll
    for (int i = 1; i < 8; i++) s += reds[i];

    const float inv = 1.f / s;
    n = 0;
    for (int j = tid; j < limit; j += 256) rowh[j] = __float2half(vals[n++] * inv);
}

// ============ add + LayerNorm -> fp16 X ============
__global__ void add_layernorm(const float* __restrict__ AE, const float* __restrict__ E,
                              const float* __restrict__ gamma, const float* __restrict__ beta,
                              __half* __restrict__ X)
{
    const int r = blockIdx.x;
    const int tid = threadIdx.x;
    float4 a = ((const float4*)(AE + (size_t)r * DM))[tid];
    float4 e = ((const float4*)(E + (size_t)r * DM))[tid];
    float x0 = a.x + e.x, x1 = a.y + e.y, x2 = a.z + e.z, x3 = a.w + e.w;
    float s = x0 + x1 + x2 + x3;
    float q = x0 * x0 + x1 * x1 + x2 * x2 + x3 * x3;
    __shared__ float rs[8], rq[8];
#pragma unroll
    for (int o = 16; o > 0; o >>= 1) {
        s += __shfl_xor_sync(0xffffffffu, s, o);
        q += __shfl_xor_sync(0xffffffffu, q, o);
    }
    if ((tid & 31) == 0) { rs[tid >> 5] = s; rq[tid >> 5] = q; }
    __syncthreads();
    s = rs[0]; q = rq[0];
#pragma unroll
    for (int i = 1; i < 8; i++) { s += rs[i]; q += rq[i]; }
    const float mean = s * (1.f / DM);
    const float var  = q * (1.f / DM) - mean * mean;
    const float inv  = rsqrtf(var + 1e-5f);
    float4 gg = ((const float4*)gamma)[tid];
    float4 bb = ((const float4*)beta)[tid];
    __half2 o0 = __floats2half2_rn((x0 - mean) * inv * gg.x + bb.x,
                                   (x1 - mean) * inv * gg.y + bb.y);
    __half2 o1 = __floats2half2_rn((x2 - mean) * inv * gg.z + bb.z,
                                   (x3 - mean) * inv * gg.w + bb.w);
    ((__half2*)(X + (size_t)r * DM))[tid * 2]     = o0;
    ((__half2*)(X + (size_t)r * DM))[tid * 2 + 1] = o1;
}

// ============ launch ============
extern "C" void kernel_launch(void* const* d_in, const int* in_sizes, int n_in,
                              void* d_out, int out_size)
{
    (void)in_sizes; (void)n_in; (void)out_size;
    const float* E     = (const float*)d_in[0];
    const float* Wq    = (const float*)d_in[1];
    const float* bq    = (const float*)d_in[2];
    const float* Wk    = (const float*)d_in[3];
    const float* bk    = (const float*)d_in[4];
    const float* Wv    = (const float*)d_in[5];
    const float* bv    = (const float*)d_in[6];
    const float* gamma = (const float*)d_in[7];
    const float* beta  = (const float*)d_in[8];
    const float* W1    = (const float*)d_in[9];
    const float* b1    = (const float*)d_in[10];
    const float* W2    = (const float*)d_in[11];
    const float* b2    = (const float*)d_in[12];
    float* out = (float*)d_out;

    __half *Eh, *QKVh, *Sh, *Xh, *Hh, *Wqkvth, *W1th, *W2th, *Vth;
    float *S, *AE, *bqkv;
    cudaGetSymbolAddress((void**)&Eh,     g_Eh);
    cudaGetSymbolAddress((void**)&QKVh,   g_QKVh);
    cudaGetSymbolAddress((void**)&S,      g_S);
    cudaGetSymbolAddress((void**)&Sh,     g_Sh);
    cudaGetSymbolAddress((void**)&AE,     g_AE);
    cudaGetSymbolAddress((void**)&Xh,     g_Xh);
    cudaGetSymbolAddress((void**)&Hh,     g_Hh);
    cudaGetSymbolAddress((void**)&Wqkvth, g_Wqkvth);
    cudaGetSymbolAddress((void**)&W1th,   g_W1th);
    cudaGetSymbolAddress((void**)&W2th,   g_W2th);
    cudaGetSymbolAddress((void**)&Vth,    g_Vth);
    cudaGetSymbolAddress((void**)&bqkv,   g_bqkv);

    dim3 tb(32, 8);
    f2h<<<(NT * DM / 4 + 255) / 256, 256>>>(E, Eh, NT * DM / 4);
    transpose_f2h<<<dim3(DM / 32, DM / 32), tb>>>(Wq, Wqkvth,             DM, DM);
    transpose_f2h<<<dim3(DM / 32, DM / 32), tb>>>(Wk, Wqkvth + 1024 * DM, DM, DM);
    transpose_f2h<<<dim3(DM / 32, DM / 32), tb>>>(Wv, Wqkvth + 2048 * DM, DM, DM);
    transpose_f2h<<<dim3(DF / 32, DM / 32), tb>>>(W1, W1th,               DF, DM);
    transpose_f2h<<<dim3(DM / 32, DF / 32), tb>>>(W2, W2th,               DM, DF);
    cudaMemcpyAsync(bqkv,        bq, DM * sizeof(float), cudaMemcpyDeviceToDevice);
    cudaMemcpyAsync(bqkv + 1024, bk, DM * sizeof(float), cudaMemcpyDeviceToDevice);
    cudaMemcpyAsync(bqkv + 2048, bv, DM * sizeof(float), cudaMemcpyDeviceToDevice);

    dim3 blk(256);

    // fused QKV projection -> half [4096, 3072]
    hgemm2<false, false, false, true, true><<<dim3(3072 / 128, NT / 128), blk>>>(
        Eh, Wqkvth, bqkv, QKVh, 3072, DM, DM, DM, 1.f);

    // S = Q @ K^T / 32 (causal lower blocks) -> fp32
    hgemm2<true, false, false, false, false><<<dim3(NT / 128, NT / 128), blk>>>(
        QKVh, QKVh + 1024, nullptr, S, NT, DM, 3072, 3072, 0.03125f);

    softmax_causal<<<NT, 256>>>(S, Sh);

    // Vth[d][t] = V[t][d]
    transpose_h2h<<<dim3(DM / 32, NT / 32), tb>>>(QKVh + 2048, Vth, 3072, NT);

    // AE = probs @ V (triangular K) -> fp32
    hgemm2<false, true, false, false, false><<<dim3(DM / 128, NT / 128), blk>>>(
        Sh, Vth, nullptr, AE, DM, NT, NT, NT, 1.f);

    add_layernorm<<<NT, 256>>>(AE, E, gamma, beta, Xh);

    // FFN
    hgemm2<false, false, true, true, true><<<dim3(DF / 128, NT / 128), blk>>>(
        Xh, W1th, b1, Hh, DF, DM, DM, DM, 1.f);
    hgemm2<false, false, false, true, false><<<dim3(DM / 128, NT / 128), blk>>>(
        Hh, W2th, b2, out, DM, DF, DF, DF, 1.f);
}

// round 11
// speedup vs baseline: 1.6094x; 1.0585x over previous
#include <cuda_runtime.h>
#include <cuda_fp16.h>
#include <cstdint>

#define NT 4096   // tokens
#define DM 1024   // model dim
#define DF 4096   // ffn dim

// ---- scratch (static device globals; allowed) ----
__device__ __half g_Eh[(size_t)NT * DM];
__device__ __half g_QKVh[(size_t)NT * 3072];      // fused Q|K|V (half), stride 3072
__device__ float  g_S[(size_t)NT * NT];           // attention scores fp32
__device__ __half g_Sh[(size_t)NT * NT];          // softmax probs half
__device__ float  g_AE[NT * DM];
__device__ __half g_Xh[NT * DM];
__device__ __half g_Hh[(size_t)NT * DF];
__device__ __half g_Wqkvth[3072 * DM];            // [3072][1024] W^T half
__device__ __half g_W1th[(size_t)DF * DM];        // [4096][1024]
__device__ __half g_W2th[(size_t)DM * DF];        // [1024][4096]
__device__ __half g_Vth[(size_t)DM * NT];         // [1024][4096] V^T half
__device__ float  g_bqkv[3072];

__device__ __forceinline__ uint32_t smem_u32(const void* p) {
    uint32_t a;
    asm("{ .reg .u64 t; cvta.to.shared.u64 t, %1; cvt.u32.u64 %0, t; }" : "=r"(a) : "l"(p));
    return a;
}
__device__ __forceinline__ void mma_f16(float* c, const uint32_t* a, const uint32_t* b) {
    asm volatile(
        "mma.sync.aligned.m16n8k16.row.col.f32.f16.f16.f32 "
        "{%0,%1,%2,%3}, {%4,%5,%6,%7}, {%8,%9}, {%0,%1,%2,%3};"
        : "+f"(c[0]), "+f"(c[1]), "+f"(c[2]), "+f"(c[3])
        : "r"(a[0]), "r"(a[1]), "r"(a[2]), "r"(a[3]), "r"(b[0]), "r"(b[1]));
}
__device__ __forceinline__ void ldsm4(uint32_t& r0, uint32_t& r1, uint32_t& r2, uint32_t& r3,
                                      uint32_t addr) {
    asm volatile("ldmatrix.sync.aligned.m8n8.x4.shared.b16 {%0,%1,%2,%3}, [%4];"
                 : "=r"(r0), "=r"(r1), "=r"(r2), "=r"(r3) : "r"(addr));
}

// ===========================================================================
// fp16 mma.sync GEMM — EXACT R8 configuration (measured 549us total; GEMMs
// sit at the legacy-HMMA issue ceiling ~0.5 HMMA/cyc/SM, so do not touch).
// Tiles 128x128x32, 256 threads = 8 warps (2 m-slabs x 4 n-slabs, 64x32),
// occ 2, LDG->STS double buffer, swizzle c_phys = c ^ ((r>>1)&3).
// ===========================================================================
template <bool CAUSAL, bool TRIK, bool RELU, bool BIAS, bool HALF_OUT>
__global__ __launch_bounds__(256, 2)
void hgemm2(const __half* __restrict__ A, const __half* __restrict__ Bt,
            const float* __restrict__ bias, void* __restrict__ Cv,
            int N, int Kdim, int lda, int ldb, float alpha)
{
    __shared__ __align__(16) uint32_t As[2][2048];
    __shared__ __align__(16) uint32_t Bs[2][2048];

    const int bx = blockIdx.x, by = blockIdx.y;
    if (CAUSAL && bx > by) return;

    const int tid  = threadIdx.x;
    const int wid  = tid >> 5;
    const int lane = tid & 31;
    const int g    = lane >> 2;
    const int tig  = lane & 3;
    const int l7   = lane & 7;
    const int q    = lane >> 3;

    const int wmt = (wid & 1) * 4;
    const int wnt = (wid >> 1) * 4;

    int kEnd = Kdim;
    if (TRIK) { int lim = (by + 1) * 128; kEnd = lim < Kdim ? lim : Kdim; }
    const int niter = kEnd >> 5;

    const int r0c = tid >> 2, c0c = tid & 3;
    const int w0 = r0c * 16 + ((c0c ^ ((r0c >> 1) & 3)) << 2);
    const int r1c = r0c + 64;
    const int w1 = r1c * 16 + ((c0c ^ ((r1c >> 1) & 3)) << 2);
    const __half* aG0 = A  + (size_t)(by * 128 + r0c) * (size_t)lda + c0c * 8;
    const __half* aG1 = A  + (size_t)(by * 128 + r1c) * (size_t)lda + c0c * 8;
    const __half* bG0 = Bt + (size_t)(bx * 128 + r0c) * (size_t)ldb + c0c * 8;
    const __half* bG1 = Bt + (size_t)(bx * 128 + r1c) * (size_t)ldb + c0c * 8;

    uint4 ra0, ra1, rb0, rb1;
#define LDG_T(k0) do { \
        ra0 = *(const uint4*)(aG0 + (k0)); \
        ra1 = *(const uint4*)(aG1 + (k0)); \
        rb0 = *(const uint4*)(bG0 + (k0)); \
        rb1 = *(const uint4*)(bG1 + (k0)); \
    } while (0)
#define STS_T(buf) do { \
        *(uint4*)&As[buf][w0] = ra0; \
        *(uint4*)&As[buf][w1] = ra1; \
        *(uint4*)&Bs[buf][w0] = rb0; \
        *(uint4*)&Bs[buf][w1] = rb1; \
    } while (0)

    const uint32_t aSm = smem_u32(As);
    const uint32_t bSm = smem_u32(Bs);

    uint32_t aOff[4][2], bOff[2][2];
#pragma unroll
    for (int m = 0; m < 4; m++) {
        int r = (wmt + m) * 16 + (q & 1) * 8 + l7;
#pragma unroll
        for (int ks = 0; ks < 2; ks++) {
            uint32_t c = (uint32_t)(2 * ks) + (uint32_t)(q >> 1);
            aOff[m][ks] = (uint32_t)r * 64u + ((c ^ ((uint32_t)(r >> 1) & 3u)) << 4);
        }
    }
#pragma unroll
    for (int p = 0; p < 2; p++) {
        int r = (wnt + 2 * p + (q >> 1)) * 8 + l7;
#pragma unroll
        for (int ks = 0; ks < 2; ks++) {
            uint32_t c = (uint32_t)(2 * ks) + (uint32_t)(q & 1);
            bOff[p][ks] = (uint32_t)r * 64u + ((c ^ ((uint32_t)(r >> 1) & 3u)) << 4);
        }
    }

    float acc[4][4][4];
#pragma unroll
    for (int i = 0; i < 4; i++)
#pragma unroll
        for (int j = 0; j < 4; j++)
#pragma unroll
            for (int t = 0; t < 4; t++) acc[i][j][t] = 0.f;

    LDG_T(0);
    STS_T(0);
    __syncthreads();

    for (int i = 0; i < niter; i++) {
        const int b = i & 1;
        if (i + 1 < niter) LDG_T((i + 1) * 32);

        const uint32_t aBase = aSm + (uint32_t)b * 8192u;
        const uint32_t bBase = bSm + (uint32_t)b * 8192u;
#pragma unroll
        for (int ks = 0; ks < 2; ks++) {
            uint32_t af[4][4], bf[4][2];
#pragma unroll
            for (int m = 0; m < 4; m++)
                ldsm4(af[m][0], af[m][1], af[m][2], af[m][3], aBase + aOff[m][ks]);
#pragma unroll
            for (int p = 0; p < 2; p++)
                ldsm4(bf[2 * p][0], bf[2 * p][1], bf[2 * p + 1][0], bf[2 * p + 1][1],
                      bBase + bOff[p][ks]);
#pragma unroll
            for (int m = 0; m < 4; m++)
#pragma unroll
                for (int n = 0; n < 4; n++)
                    mma_f16(acc[m][n], af[m], bf[n]);
        }

        if (i + 1 < niter) STS_T(b ^ 1);
        __syncthreads();
    }

    // ---- epilogue ----
    const int rowBase = by * 128 + (wid & 1) * 64 + g;
    const int colBase = bx * 128 + (wid >> 1) * 32 + tig * 2;
#pragma unroll
    for (int m = 0; m < 4; m++) {
        const int r0 = rowBase + m * 16;
#pragma unroll
        for (int n = 0; n < 4; n++) {
            const int col = colBase + n * 8;
            float b0 = 0.f, b1 = 0.f;
            if (BIAS) { b0 = bias[col]; b1 = bias[col + 1]; }
            float v0x = acc[m][n][0] * alpha + b0;
            float v0y = acc[m][n][1] * alpha + b1;
            float v1x = acc[m][n][2] * alpha + b0;
            float v1y = acc[m][n][3] * alpha + b1;
            if (RELU) {
                v0x = fmaxf(v0x, 0.f); v0y = fmaxf(v0y, 0.f);
                v1x = fmaxf(v1x, 0.f); v1y = fmaxf(v1y, 0.f);
            }
            if (HALF_OUT) {
                __half* C = (__half*)Cv;
                *(__half2*)(C + (size_t)r0 * N + col)       = __floats2half2_rn(v0x, v0y);
                *(__half2*)(C + (size_t)(r0 + 8) * N + col) = __floats2half2_rn(v1x, v1y);
            } else {
                float* C = (float*)Cv;
                *(float2*)(C + (size_t)r0 * N + col)       = make_float2(v0x, v0y);
                *(float2*)(C + (size_t)(r0 + 8) * N + col) = make_float2(v1x, v1y);
            }
        }
    }
#undef LDG_T
#undef STS_T
}

// ===========================================================================
// Merged prologue: ONE launch does f2h(E), Wq/Wk/Wv -> Wqkvth (transposed,
// half), W1 -> W1th, W2 -> W2th, and bias concat. All pieces independent.
// Block-range dispatch over a flat 1D grid of 256-thread blocks:
//   [0, 4096)          : f2h E           (1M float4, one per thread)
//   [4096, 7168)       : Wq/Wk/Wv transposes (3 x 1024 tile-blocks of 32x32)
//   [7168, 11264)      : W1 transpose    (4096 tile-blocks: 128 x 32)
//   [11264, 15360)     : W2 transpose    (4096 tile-blocks: 32 x 128)
//   [15360, 15372)     : bias concat     (12 x 256 = 3072 floats)
// ===========================================================================
__device__ __forceinline__ void tile_transpose_f2h(
    const float* __restrict__ in, __half* __restrict__ out,
    int inS, int outS, int bcx, int bry, int tid)
{
    __shared__ float t[32][33];
    const int x = tid & 31, y = tid >> 5;       // 32 x 8
    const int bc = bcx * 32, br = bry * 32;
#pragma unroll
    for (int j = 0; j < 32; j += 8)
        t[y + j][x] = in[(size_t)(br + y + j) * inS + bc + x];
    __syncthreads();
#pragma unroll
    for (int j = 0; j < 32; j += 8)
        out[(size_t)(bc + y + j) * outS + br + x] = __float2half(t[x][y + j]);
}

__global__ __launch_bounds__(256)
void prep(const float* __restrict__ E,
          const float* __restrict__ Wq, const float* __restrict__ Wk,
          const float* __restrict__ Wv,
          const float* __restrict__ W1, const float* __restrict__ W2,
          const float* __restrict__ bq, const float* __restrict__ bk,
          const float* __restrict__ bv,
          __half* __restrict__ Eh, __half* __restrict__ Wqkvth,
          __half* __restrict__ W1th, __half* __restrict__ W2th,
          float* __restrict__ bqkv)
{
    const int bid = blockIdx.x;
    const int tid = threadIdx.x;

    if (bid < 4096) {                         // f2h E
        int i = bid * 256 + tid;              // < 1M float4
        float4 v = ((const float4*)E)[i];
        ((__half2*)Eh)[i * 2]     = __floats2half2_rn(v.x, v.y);
        ((__half2*)Eh)[i * 2 + 1] = __floats2half2_rn(v.z, v.w);
    } else if (bid < 7168) {                  // QKV weight transposes
        int t = bid - 4096;
        int which = t >> 10;                  // 0..2
        int tt = t & 1023;
        const float* src = (which == 0) ? Wq : (which == 1) ? Wk : Wv;
        __half* dst = Wqkvth + (size_t)which * 1024 * DM;
        tile_transpose_f2h(src, dst, DM, DM, tt & 31, tt >> 5, tid);
    } else if (bid < 11264) {                 // W1 [1024,4096] -> W1th [4096,1024]
        int t = bid - 7168;
        tile_transpose_f2h(W1, W1th, DF, DM, t & 127, t >> 7, tid);
    } else if (bid < 15360) {                 // W2 [4096,1024] -> W2th [1024,4096]
        int t = bid - 11264;
        tile_transpose_f2h(W2, W2th, DM, DF, t & 31, t >> 5, tid);
    } else {                                  // bias concat
        int i = (bid - 15360) * 256 + tid;    // < 3072
        float v = (i < 1024) ? bq[i] : (i < 2048) ? bk[i - 1024] : bv[i - 2048];
        bqkv[i] = v;
    }
}

// ============ transpose fp16 -> fp16 (Vth) ============
__global__ void transpose_h2h(const __half* __restrict__ in, __half* __restrict__ out,
                              int inS, int outS)
{
    __shared__ __half t[32][34];
    const int bc = blockIdx.x * 32;
    const int br = blockIdx.y * 32;
    const int x = threadIdx.x, y = threadIdx.y;
#pragma unroll
    for (int j = 0; j < 32; j += 8)
        t[y + j][x] = in[(size_t)(br + y + j) * inS + bc + x];
    __syncthreads();
#pragma unroll
    for (int j = 0; j < 32; j += 8)
        out[(size_t)(bc + y + j) * outS + br + x] = t[x][y + j];
}

// ============ fast exp (FMA pipe) ============
__device__ __forceinline__ float fast_exp(float x) {
    float y = x * 1.4426950408889634f;
    float n = rintf(y);
    float f = y - n;
    float p = 1.5403530393e-4f;
    p = fmaf(p, f, 1.3333558146e-3f);
    p = fmaf(p, f, 9.6181291076e-3f);
    p = fmaf(p, f, 5.5504108665e-2f);
    p = fmaf(p, f, 2.4022650696e-1f);
    p = fmaf(p, f, 6.9314718056e-1f);
    p = fmaf(p, f, 1.0f);
    float ec = fmaxf(n, -126.f);
    return __int_as_float(((int)ec + 127) << 23) * p;
}

// ============ causal softmax: fp32 scores -> fp16 probs (zero-padded) ============
__global__ void softmax_causal(const float* __restrict__ S, __half* __restrict__ Sh)
{
    const int r = blockIdx.x;
    const int tid = threadIdx.x;
    const int limit = ((r >> 7) + 1) << 7;
    const float* row = S + (size_t)r * NT;
    __half* rowh = Sh + (size_t)r * NT;

    float vals[16];
    int n = 0;
    float m = -1e30f;
    for (int j = tid; j < limit; j += 256) {
        float v = (j <= r) ? row[j] : -1e30f;
        vals[n++] = v;
        m = fmaxf(m, v);
    }
    __shared__ float redm[8], reds[8];
#pragma unroll
    for (int o = 16; o > 0; o >>= 1) m = fmaxf(m, __shfl_xor_sync(0xffffffffu, m, o));
    if ((tid & 31) == 0) redm[tid >> 5] = m;
    __syncthreads();
    m = redm[0];
#pragma unroll
    for (int i = 1; i < 8; i++) m = fmaxf(m, redm[i]);

    float s = 0.f;
    for (int i = 0; i < n; i++) { float e = fast_exp(vals[i] - m); vals[i] = e; s += e; }
#pragma unroll
    for (int o = 16; o > 0; o >>= 1) s += __shfl_xor_sync(0xffffffffu, s, o);
    if ((tid & 31) == 0) reds[tid >> 5] = s;
    __syncthreads();
    s = reds[0];
#pragma unroll
    for (int i = 1; i < 8; i++) s += reds[i];

    const float inv = 1.f / s;
    n = 0;
    for (int j = tid; j < limit; j += 256) rowh[j] = __float2half(vals[n++] * inv);
}

// ============ add + LayerNorm -> fp16 X ============
__global__ void add_layernorm(const float* __restrict__ AE, const float* __restrict__ E,
                              const float* __restrict__ gamma, const float* __restrict__ beta,
                              __half* __restrict__ X)
{
    const int r = blockIdx.x;
    const int tid = threadIdx.x;
    float4 a = ((const float4*)(AE + (size_t)r * DM))[tid];
    float4 e = ((const float4*)(E + (size_t)r * DM))[tid];
    float x0 = a.x + e.x, x1 = a.y + e.y, x2 = a.z + e.z, x3 = a.w + e.w;
    float s = x0 + x1 + x2 + x3;
    float q = x0 * x0 + x1 * x1 + x2 * x2 + x3 * x3;
    __shared__ float rs[8], rq[8];
#pragma unroll
    for (int o = 16; o > 0; o >>= 1) {
        s += __shfl_xor_sync(0xffffffffu, s, o);
        q += __shfl_xor_sync(0xffffffffu, q, o);
    }
    if ((tid & 31) == 0) { rs[tid >> 5] = s; rq[tid >> 5] = q; }
    __syncthreads();
    s = rs[0]; q = rq[0];
#pragma unroll
    for (int i = 1; i < 8; i++) { s += rs[i]; q += rq[i]; }
    const float mean = s * (1.f / DM);
    const float var  = q * (1.f / DM) - mean * mean;
    const float inv  = rsqrtf(var + 1e-5f);
    float4 gg = ((const float4*)gamma)[tid];
    float4 bb = ((const float4*)beta)[tid];
    __half2 o0 = __floats2half2_rn((x0 - mean) * inv * gg.x + bb.x,
                                   (x1 - mean) * inv * gg.y + bb.y);
    __half2 o1 = __floats2half2_rn((x2 - mean) * inv * gg.z + bb.z,
                                   (x3 - mean) * inv * gg.w + bb.w);
    ((__half2*)(X + (size_t)r * DM))[tid * 2]     = o0;
    ((__half2*)(X + (size_t)r * DM))[tid * 2 + 1] = o1;
}

// ============ launch ============
extern "C" void kernel_launch(void* const* d_in, const int* in_sizes, int n_in,
                              void* d_out, int out_size)
{
    (void)in_sizes; (void)n_in; (void)out_size;
    const float* E     = (const float*)d_in[0];
    const float* Wq    = (const float*)d_in[1];
    const float* bq    = (const float*)d_in[2];
    const float* Wk    = (const float*)d_in[3];
    const float* bk    = (const float*)d_in[4];
    const float* Wv    = (const float*)d_in[5];
    const float* bv    = (const float*)d_in[6];
    const float* gamma = (const float*)d_in[7];
    const float* beta  = (const float*)d_in[8];
    const float* W1    = (const float*)d_in[9];
    const float* b1    = (const float*)d_in[10];
    const float* W2    = (const float*)d_in[11];
    const float* b2    = (const float*)d_in[12];
    float* out = (float*)d_out;

    __half *Eh, *QKVh, *Sh, *Xh, *Hh, *Wqkvth, *W1th, *W2th, *Vth;
    float *S, *AE, *bqkv;
    cudaGetSymbolAddress((void**)&Eh,     g_Eh);
    cudaGetSymbolAddress((void**)&QKVh,   g_QKVh);
    cudaGetSymbolAddress((void**)&S,      g_S);
    cudaGetSymbolAddress((void**)&Sh,     g_Sh);
    cudaGetSymbolAddress((void**)&AE,     g_AE);
    cudaGetSymbolAddress((void**)&Xh,     g_Xh);
    cudaGetSymbolAddress((void**)&Hh,     g_Hh);
    cudaGetSymbolAddress((void**)&Wqkvth, g_Wqkvth);
    cudaGetSymbolAddress((void**)&W1th,   g_W1th);
    cudaGetSymbolAddress((void**)&W2th,   g_W2th);
    cudaGetSymbolAddress((void**)&Vth,    g_Vth);
    cudaGetSymbolAddress((void**)&bqkv,   g_bqkv);

    // ONE merged prologue launch (f2h + 5 weight transposes + bias concat)
    prep<<<15372, 256>>>(E, Wq, Wk, Wv, W1, W2, bq, bk, bv,
                         Eh, Wqkvth, W1th, W2th, bqkv);

    dim3 blk(256);
    dim3 tb(32, 8);

    // fused QKV projection -> half [4096, 3072]
    hgemm2<false, false, false, true, true><<<dim3(3072 / 128, NT / 128), blk>>>(
        Eh, Wqkvth, bqkv, QKVh, 3072, DM, DM, DM, 1.f);

    // Vth[d][t] = V[t][d]  (depends only on QKV)
    transpose_h2h<<<dim3(DM / 32, NT / 32), tb>>>(QKVh + 2048, Vth, 3072, NT);

    // S = Q @ K^T / 32 (causal lower blocks) -> fp32
    hgemm2<true, false, false, false, false><<<dim3(NT / 128, NT / 128), blk>>>(
        QKVh, QKVh + 1024, nullptr, S, NT, DM, 3072, 3072, 0.03125f);

    softmax_causal<<<NT, 256>>>(S, Sh);

    // AE = probs @ V (triangular K) -> fp32
    hgemm2<false, true, false, false, false><<<dim3(DM / 128, NT / 128), blk>>>(
        Sh, Vth, nullptr, AE, DM, NT, NT, NT, 1.f);

    add_layernorm<<<NT, 256>>>(AE, E, gamma, beta, Xh);

    // FFN
    hgemm2<false, false, true, true, true><<<dim3(DF / 128, NT / 128), blk>>>(
        Xh, W1th, b1, Hh, DF, DM, DM, DM, 1.f);
    hgemm2<false, false, false, true, false><<<dim3(DM / 128, NT / 128), blk>>>(
        Hh, W2th, b2, out, DM, DF, DF, DF, 1.f);
}